// round 14
// baseline (speedup 1.0000x reference)
#include <cuda_runtime.h>
#include <cstdint>

// Problem dims
#define Bn 256
#define Tn 512
#define In 256
#define Hn 1024
#define On 128
#define Gn 2048   // 2*H

#define RGRID 128            // recurrence CTAs
#define OGRID 16             // output-GEMV CTAs (consumers only)
#define TGRID (RGRID + OGRID)
#define ARRIVALS (RGRID * 8) // one release per recurrence WARP per step

// Scratch (static device globals — no allocation)
__device__ float              g_Xp[Bn * Gn];   // 2 MB : x-projection + Bih
__device__ unsigned long long g_hx[2][Hn];     // (tag<<32)|bits(h), dbl-buffered
__device__ float              g_lasts[Bn * Hn];// 1 MB : h after each step
__device__ unsigned           g_bar[Bn];       // per-step counters (out-CTAs)

// ---------------------------------------------------------------------------
// helpers
// ---------------------------------------------------------------------------
__device__ __forceinline__ void ffma2(unsigned long long& d,
                                      unsigned long long a,
                                      unsigned long long b) {
    asm("fma.rn.f32x2 %0, %1, %2, %0;" : "+l"(d) : "l"(a), "l"(b));
}
__device__ __forceinline__ float2 u2f(unsigned long long v) {
    float2 f; asm("mov.b64 {%0,%1}, %2;" : "=f"(f.x), "=f"(f.y) : "l"(v));
    return f;
}
__device__ __forceinline__ float4 ldcg_v4(const float4* p) {
    float4 v;
    asm volatile("ld.global.cg.v4.f32 {%0,%1,%2,%3}, [%4];"
                 : "=f"(v.x), "=f"(v.y), "=f"(v.z), "=f"(v.w)
                 : "l"(p) : "memory");
    return v;
}
// single-access 64-bit atoms (value+tag travel together — never torn)
__device__ __forceinline__ unsigned long long ld_relaxed_u64(
        const unsigned long long* p) {
    unsigned long long v;
    asm volatile("ld.relaxed.gpu.global.b64 %0, [%1];"
                 : "=l"(v) : "l"(p) : "memory");
    return v;
}
__device__ __forceinline__ void st_relaxed_u64(unsigned long long* p,
                                               unsigned long long v) {
    asm volatile("st.relaxed.gpu.global.b64 [%0], %1;"
                 :: "l"(p), "l"(v) : "memory");
}
__device__ __forceinline__ void bar_arrive_release(unsigned* p) {
    asm volatile("red.release.gpu.global.add.u32 [%0], 1;" :: "l"(p) : "memory");
}
__device__ __forceinline__ unsigned ld_acquire_gpu(const unsigned* p) {
    unsigned v;
    asm volatile("ld.acquire.gpu.global.u32 %0, [%1];" : "=r"(v) : "l"(p) : "memory");
    return v;
}

// ---------------------------------------------------------------------------
// Phase 0: Xp[b, j] = dot(inputs[b, T-1, :], Wih[j, :]) + Bih[j]
// Register-tiled GEMM: grid (32 j-tiles of 64, 8 b-tiles of 32), 256 threads.
// Block (0,0) resets the tag buffers + counters so graph replays are
// deterministic.
// ---------------------------------------------------------------------------
__global__ void __launch_bounds__(256) xproj_kernel(
    const float* __restrict__ inputs, const float* __restrict__ Wih,
    const float* __restrict__ Bih)
{
    __shared__ float4 Xs4[32 * 65];          // 32 rows x 260 floats (pad 4)
    const int tid  = threadIdx.x;
    const int lane = tid & 31;
    const int jg   = tid >> 5;
    const int b0   = blockIdx.y * 32;

    if (blockIdx.x == 0 && blockIdx.y == 0) {
        g_bar[tid] = 0u;                     // 256 counters
        #pragma unroll
        for (int i = 0; i < 4; ++i) {        // 2 x 1024 u64, tag=0 value=0
            g_hx[0][tid + i * 256] = 0ull;
            g_hx[1][tid + i * 256] = 0ull;
        }
    }

    // Stage 32 input rows (last timestep of each b)
    #pragma unroll
    for (int i = 0; i < 8; ++i) {
        const int idx = tid + i * 256;       // 0..2047
        const int r   = idx >> 6;
        const int c4  = idx & 63;
        Xs4[r * 65 + c4] = ldcg_v4(reinterpret_cast<const float4*>(
            inputs + ((size_t)(b0 + r) * Tn + (Tn - 1)) * In) + c4);
    }
    __syncthreads();

    const int j0 = blockIdx.x * 64 + jg * 8;
    const float4* W4 = reinterpret_cast<const float4*>(Wih);

    unsigned long long acc[8][2];
    #pragma unroll
    for (int k = 0; k < 8; ++k) { acc[k][0] = 0ull; acc[k][1] = 0ull; }

    #pragma unroll 4
    for (int c4 = 0; c4 < 64; ++c4) {
        const float4 xv = Xs4[lane * 65 + c4];
        const ulonglong2 xu = *reinterpret_cast<const ulonglong2*>(&xv);
        #pragma unroll
        for (int k = 0; k < 8; ++k) {
            const float4 wv = __ldg(W4 + (size_t)(j0 + k) * 64 + c4);
            const ulonglong2 wu = *reinterpret_cast<const ulonglong2*>(&wv);
            ffma2(acc[k][0], wu.x, xu.x);
            ffma2(acc[k][1], wu.y, xu.y);
        }
    }

    float* dst = g_Xp + (size_t)(b0 + lane) * Gn + j0;
    #pragma unroll
    for (int k = 0; k < 8; ++k) {
        const float2 s0 = u2f(acc[k][0]);
        const float2 s1 = u2f(acc[k][1]);
        dst[k] = (s0.x + s0.y) + (s1.x + s1.y) + __ldg(Bih + j0 + k);
    }
}

// ---------------------------------------------------------------------------
// Phase 1+2 fused persistent kernel. IDENTICAL to the R9 passing version
// (128 CTAs x 256 thr, f32x2 dot, both __syncthreads, per-warp
// single-address red.release right after the publish) EXCEPT the poll:
// DUAL-WAVE polling — two independent register sets of 4 loads alternately
// checked/reissued, so ~8 loads stay outstanding and the tag-sampling
// period halves (RT/2 instead of RT). Discovery latency drops ~0.25-0.5 RT.
//   CTAs [0,128): recurrence, warp owns j = cta*8 + w.
//   CTAs [128,144): output GEMV, warp owns o; spins on g_bar[b] reaching
//     ARRIVALS, then out[b,o] = dot(lasts[b,:], Wout[o,:]) + Bout[o].
// ---------------------------------------------------------------------------
__global__ void __launch_bounds__(256, 1) recur_kernel(
    const float* __restrict__ Whh, const float* __restrict__ Bhh,
    const float* __restrict__ Wout, const float* __restrict__ Bout,
    float* __restrict__ out)
{
    const int tid  = threadIdx.x;
    const int lane = tid & 31;
    const int w    = tid >> 5;

    if (blockIdx.x < RGRID) {
        // ----------------- recurrence role -----------------
        __shared__ float4 hs4[Hn / 4];            // 4 KB h staging (values only)
        const int j = blockIdx.x * 8 + w;         // 0..1023

        // Whh rows in registers as f32x2 pairs
        ulonglong2 wfu[8], whu[8];
        #pragma unroll
        for (int c = 0; c < 8; ++c) {
            float4 t0 = __ldg(reinterpret_cast<const float4*>(
                              Whh + (size_t)j * Hn) + c * 32 + lane);
            float4 t1 = __ldg(reinterpret_cast<const float4*>(
                              Whh + (size_t)(j + Hn) * Hn) + c * 32 + lane);
            wfu[c] = *reinterpret_cast<const ulonglong2*>(&t0);
            whu[c] = *reinterpret_cast<const ulonglong2*>(&t1);
        }
        const float bf = __ldg(Bhh + j);
        const float bh = __ldg(Bhh + j + Hn);

        float xf = __ldg(&g_Xp[j]);
        float xh = __ldg(&g_Xp[Hn + j]);

        for (int b = 0; b < Bn; ++b) {
            // --- DUAL-WAVE poll of tagged h atoms (thread owns 4 elements)
            const unsigned tag = (unsigned)b;
            const unsigned long long* src = &g_hx[b & 1][4 * tid];
            unsigned long long e0, e1, e2, e3;
            {
                // wave A and wave B both in flight (8 outstanding loads)
                unsigned long long a0 = ld_relaxed_u64(src + 0);
                unsigned long long a1 = ld_relaxed_u64(src + 1);
                unsigned long long a2 = ld_relaxed_u64(src + 2);
                unsigned long long a3 = ld_relaxed_u64(src + 3);
                unsigned long long c0 = ld_relaxed_u64(src + 0);
                unsigned long long c1 = ld_relaxed_u64(src + 1);
                unsigned long long c2 = ld_relaxed_u64(src + 2);
                unsigned long long c3 = ld_relaxed_u64(src + 3);
                for (;;) {
                    if ((unsigned)(a0 >> 32) == tag &&
                        (unsigned)(a1 >> 32) == tag &&
                        (unsigned)(a2 >> 32) == tag &&
                        (unsigned)(a3 >> 32) == tag) {
                        e0 = a0; e1 = a1; e2 = a2; e3 = a3; break;
                    }
                    a0 = ld_relaxed_u64(src + 0);
                    a1 = ld_relaxed_u64(src + 1);
                    a2 = ld_relaxed_u64(src + 2);
                    a3 = ld_relaxed_u64(src + 3);
                    if ((unsigned)(c0 >> 32) == tag &&
                        (unsigned)(c1 >> 32) == tag &&
                        (unsigned)(c2 >> 32) == tag &&
                        (unsigned)(c3 >> 32) == tag) {
                        e0 = c0; e1 = c1; e2 = c2; e3 = c3; break;
                    }
                    c0 = ld_relaxed_u64(src + 0);
                    c1 = ld_relaxed_u64(src + 1);
                    c2 = ld_relaxed_u64(src + 2);
                    c3 = ld_relaxed_u64(src + 3);
                }
            }
            hs4[tid] = make_float4(__uint_as_float((unsigned)e0),
                                   __uint_as_float((unsigned)e1),
                                   __uint_as_float((unsigned)e2),
                                   __uint_as_float((unsigned)e3));
            __syncthreads();

            // --- dual dot products with packed f32x2 FMAs
            const ulonglong2* hsu = reinterpret_cast<const ulonglong2*>(hs4);
            unsigned long long af01 = 0ull, af23 = 0ull, ah01 = 0ull, ah23 = 0ull;
            #pragma unroll
            for (int c = 0; c < 8; ++c) {
                const ulonglong2 hv = hsu[c * 32 + lane];   // LDS.128
                ffma2(af01, wfu[c].x, hv.x);
                ffma2(af23, wfu[c].y, hv.y);
                ffma2(ah01, whu[c].x, hv.x);
                ffma2(ah23, whu[c].y, hv.y);
            }
            const float2 fa = u2f(af01), fb = u2f(af23);
            const float2 ga = u2f(ah01), gb = u2f(ah23);
            float af = (fa.x + fa.y) + (fb.x + fb.y);
            float ah = (ga.x + ga.y) + (gb.x + gb.y);

            const float hprev = reinterpret_cast<const float*>(hs4)[j];

            // prefetch next step's Xp — hides under reduce + poll
            float xf_n = 0.f, xh_n = 0.f;
            if (b + 1 < Bn) {
                xf_n = __ldg(&g_Xp[(size_t)(b + 1) * Gn + j]);
                xh_n = __ldg(&g_Xp[(size_t)(b + 1) * Gn + Hn + j]);
            }

            #pragma unroll
            for (int off = 16; off > 0; off >>= 1) {
                af += __shfl_xor_sync(0xffffffffu, af, off);
                ah += __shfl_xor_sync(0xffffffffu, ah, off);
            }

            // fast gating (error ~1e-6, tolerance 1e-3)
            const float fz = xf + af + bf;
            const float fG = __fdividef(1.0f, 1.0f + __expf(-fz));
            float ta = xh + fG * (ah + bh);
            ta = fminf(fmaxf(ta, -15.f), 15.f);
            const float e2v = __expf(2.0f * ta);
            const float hG = __fdividef(e2v - 1.0f, e2v + 1.0f);
            const float hnew = fmaf(fG, hG - hprev, hprev);

            if (lane == 0) {
                // publish (tag<<32 | value) as ONE 64-bit atom — never torn.
                // single-address red.release right after: forces drain AND
                // paces the grid (R10/R12/R13 evidence: both matter).
                const unsigned long long atom =
                    ((unsigned long long)(unsigned)(b + 1) << 32) |
                    (unsigned long long)__float_as_uint(hnew);
                st_relaxed_u64(&g_hx[(b + 1) & 1][j], atom);
                g_lasts[(size_t)b * Hn + j] = hnew;
                bar_arrive_release(&g_bar[b]);     // for out-CTAs only
            }
            __syncthreads();   // all warps done reading hs4 before next stage

            xf = xf_n; xh = xh_n;
        }
    } else {
        // ----------------- output GEMV role -----------------
        const int o = (blockIdx.x - RGRID) * 8 + w;    // 0..127

        float4 wv[8];
        #pragma unroll
        for (int c = 0; c < 8; ++c)
            wv[c] = __ldg(reinterpret_cast<const float4*>(
                          Wout + (size_t)o * Hn) + c * 32 + lane);
        const float bo = __ldg(Bout + o);

        for (int b = 0; b < Bn; ++b) {
            if (tid == 0) {
                // ARRIVALS = RGRID*8: one release per recurrence warp
                while (ld_acquire_gpu(&g_bar[b]) < (unsigned)ARRIVALS) {}
            }
            __syncthreads();

            const float4* lr = reinterpret_cast<const float4*>(
                g_lasts + (size_t)b * Hn);
            float a0 = 0.f, a1 = 0.f, a2 = 0.f, a3 = 0.f;
            #pragma unroll
            for (int c = 0; c < 8; ++c) {
                const float4 lv = __ldcg(lr + c * 32 + lane);
                a0 = fmaf(wv[c].x, lv.x, a0);
                a1 = fmaf(wv[c].y, lv.y, a1);
                a2 = fmaf(wv[c].z, lv.z, a2);
                a3 = fmaf(wv[c].w, lv.w, a3);
            }
            float acc = (a0 + a1) + (a2 + a3);
            #pragma unroll
            for (int off = 16; off > 0; off >>= 1)
                acc += __shfl_xor_sync(0xffffffffu, acc, off);
            if (lane == 0) out[(size_t)b * On + o] = acc + bo;
        }
    }
}

// ---------------------------------------------------------------------------
extern "C" void kernel_launch(void* const* d_in, const int* in_sizes, int n_in,
                              void* d_out, int out_size) {
    const float* inputs = (const float*)d_in[0];
    const float* Wih    = (const float*)d_in[1];
    const float* Whh    = (const float*)d_in[2];
    const float* Bih    = (const float*)d_in[3];
    const float* Bhh    = (const float*)d_in[4];
    const float* Wout   = (const float*)d_in[5];
    const float* Bout   = (const float*)d_in[6];
    float* out = (float*)d_out;

    xproj_kernel<<<dim3(32, 8), 256>>>(inputs, Wih, Bih);
    recur_kernel<<<TGRID, 256>>>(Whh, Bhh, Wout, Bout, out);
}

// round 15
// speedup vs baseline: 1.4938x; 1.4938x over previous
#include <cuda_runtime.h>
#include <cstdint>

// Problem dims
#define Bn 256
#define Tn 512
#define In 256
#define Hn 1024
#define On 128
#define Gn 2048   // 2*H

#define RGRID 128            // recurrence CTAs
#define OGRID 16             // output-GEMV CTAs (consumers only)
#define TGRID (RGRID + OGRID)
#define ARRIVALS (RGRID * 8) // one release per recurrence WARP per step

// Scratch (static device globals — no allocation)
__device__ float              g_Xp[Bn * Gn];   // 2 MB : x-projection + Bih
__device__ unsigned long long g_hx[2][Hn];     // (tag<<32)|bits(h), dbl-buffered
__device__ float              g_lasts[Bn * Hn];// 1 MB : h after each step
__device__ unsigned           g_bar[Bn];       // per-step counters (out-CTAs)

// ---------------------------------------------------------------------------
// helpers
// ---------------------------------------------------------------------------
__device__ __forceinline__ void ffma2(unsigned long long& d,
                                      unsigned long long a,
                                      unsigned long long b) {
    asm("fma.rn.f32x2 %0, %1, %2, %0;" : "+l"(d) : "l"(a), "l"(b));
}
__device__ __forceinline__ float2 u2f(unsigned long long v) {
    float2 f; asm("mov.b64 {%0,%1}, %2;" : "=f"(f.x), "=f"(f.y) : "l"(v));
    return f;
}
__device__ __forceinline__ float4 ldcg_v4(const float4* p) {
    float4 v;
    asm volatile("ld.global.cg.v4.f32 {%0,%1,%2,%3}, [%4];"
                 : "=f"(v.x), "=f"(v.y), "=f"(v.z), "=f"(v.w)
                 : "l"(p) : "memory");
    return v;
}
// single-access 64-bit atoms (value+tag travel together — never torn)
__device__ __forceinline__ unsigned long long ld_relaxed_u64(
        const unsigned long long* p) {
    unsigned long long v;
    asm volatile("ld.relaxed.gpu.global.b64 %0, [%1];"
                 : "=l"(v) : "l"(p) : "memory");
    return v;
}
__device__ __forceinline__ void st_relaxed_u64(unsigned long long* p,
                                               unsigned long long v) {
    asm volatile("st.relaxed.gpu.global.b64 [%0], %1;"
                 :: "l"(p), "l"(v) : "memory");
}
__device__ __forceinline__ void bar_arrive_release(unsigned* p) {
    asm volatile("red.release.gpu.global.add.u32 [%0], 1;" :: "l"(p) : "memory");
}
__device__ __forceinline__ unsigned ld_acquire_gpu(const unsigned* p) {
    unsigned v;
    asm volatile("ld.acquire.gpu.global.u32 %0, [%1];" : "=r"(v) : "l"(p) : "memory");
    return v;
}

// ---------------------------------------------------------------------------
// Phase 0: Xp[b, j] = dot(inputs[b, T-1, :], Wih[j, :]) + Bih[j]
// Register-tiled GEMM: grid (32 j-tiles of 64, 8 b-tiles of 32), 256 threads.
// Block (0,0) resets the tag buffers + counters so graph replays are
// deterministic.
// ---------------------------------------------------------------------------
__global__ void __launch_bounds__(256) xproj_kernel(
    const float* __restrict__ inputs, const float* __restrict__ Wih,
    const float* __restrict__ Bih)
{
    __shared__ float4 Xs4[32 * 65];          // 32 rows x 260 floats (pad 4)
    const int tid  = threadIdx.x;
    const int lane = tid & 31;
    const int jg   = tid >> 5;
    const int b0   = blockIdx.y * 32;

    if (blockIdx.x == 0 && blockIdx.y == 0) {
        g_bar[tid] = 0u;                     // 256 counters
        #pragma unroll
        for (int i = 0; i < 4; ++i) {        // 2 x 1024 u64, tag=0 value=0
            g_hx[0][tid + i * 256] = 0ull;
            g_hx[1][tid + i * 256] = 0ull;
        }
    }

    // Stage 32 input rows (last timestep of each b)
    #pragma unroll
    for (int i = 0; i < 8; ++i) {
        const int idx = tid + i * 256;       // 0..2047
        const int r   = idx >> 6;
        const int c4  = idx & 63;
        Xs4[r * 65 + c4] = ldcg_v4(reinterpret_cast<const float4*>(
            inputs + ((size_t)(b0 + r) * Tn + (Tn - 1)) * In) + c4);
    }
    __syncthreads();

    const int j0 = blockIdx.x * 64 + jg * 8;
    const float4* W4 = reinterpret_cast<const float4*>(Wih);

    unsigned long long acc[8][2];
    #pragma unroll
    for (int k = 0; k < 8; ++k) { acc[k][0] = 0ull; acc[k][1] = 0ull; }

    #pragma unroll 4
    for (int c4 = 0; c4 < 64; ++c4) {
        const float4 xv = Xs4[lane * 65 + c4];
        const ulonglong2 xu = *reinterpret_cast<const ulonglong2*>(&xv);
        #pragma unroll
        for (int k = 0; k < 8; ++k) {
            const float4 wv = __ldg(W4 + (size_t)(j0 + k) * 64 + c4);
            const ulonglong2 wu = *reinterpret_cast<const ulonglong2*>(&wv);
            ffma2(acc[k][0], wu.x, xu.x);
            ffma2(acc[k][1], wu.y, xu.y);
        }
    }

    float* dst = g_Xp + (size_t)(b0 + lane) * Gn + j0;
    #pragma unroll
    for (int k = 0; k < 8; ++k) {
        const float2 s0 = u2f(acc[k][0]);
        const float2 s1 = u2f(acc[k][1]);
        dst[k] = (s0.x + s0.y) + (s1.x + s1.y) + __ldg(Bih + j0 + k);
    }
}

// ---------------------------------------------------------------------------
// Phase 1+2 fused persistent kernel — the R9 configuration (proven local
// optimum over 5 falsified perturbations): 128 CTAs x 256 thr, single-wave
// parallel 4-atom poll, f32x2 dot, both __syncthreads, per-warp
// single-address red.release immediately after the tagged publish
// (drain-forcer + grid pacer). Local trims only: hprev carried in a
// register (hnew is computed identically on all lanes), Xp pointer hoisted.
//   CTAs [0,128): recurrence, warp owns j = cta*8 + w.
//   CTAs [128,144): output GEMV, warp owns o; spins on g_bar[b] reaching
//     ARRIVALS, then out[b,o] = dot(lasts[b,:], Wout[o,:]) + Bout[o].
// ---------------------------------------------------------------------------
__global__ void __launch_bounds__(256, 1) recur_kernel(
    const float* __restrict__ Whh, const float* __restrict__ Bhh,
    const float* __restrict__ Wout, const float* __restrict__ Bout,
    float* __restrict__ out)
{
    const int tid  = threadIdx.x;
    const int lane = tid & 31;
    const int w    = tid >> 5;

    if (blockIdx.x < RGRID) {
        // ----------------- recurrence role -----------------
        __shared__ float4 hs4[Hn / 4];            // 4 KB h staging (values only)
        const int j = blockIdx.x * 8 + w;         // 0..1023

        // Whh rows in registers as f32x2 pairs
        ulonglong2 wfu[8], whu[8];
        #pragma unroll
        for (int c = 0; c < 8; ++c) {
            float4 t0 = __ldg(reinterpret_cast<const float4*>(
                              Whh + (size_t)j * Hn) + c * 32 + lane);
            float4 t1 = __ldg(reinterpret_cast<const float4*>(
                              Whh + (size_t)(j + Hn) * Hn) + c * 32 + lane);
            wfu[c] = *reinterpret_cast<const ulonglong2*>(&t0);
            whu[c] = *reinterpret_cast<const ulonglong2*>(&t1);
        }
        const float bf = __ldg(Bhh + j);
        const float bh = __ldg(Bhh + j + Hn);

        // Xp pointers hoisted; first step's values prefetched
        const float* xpf = g_Xp + j;          // row stride Gn
        const float* xph = g_Xp + Hn + j;
        float xf = __ldg(xpf);
        float xh = __ldg(xph);

        float hprev = 0.0f;                   // own h[j], carried in register

        for (int b = 0; b < Bn; ++b) {
            // --- PARALLEL poll of tagged h atoms (thread owns 4 elements):
            // all four loads in flight together — ~1 L2 RT per pass.
            const unsigned tag = (unsigned)b;
            const unsigned long long* src = &g_hx[b & 1][4 * tid];
            unsigned long long e0 = ld_relaxed_u64(src + 0);
            unsigned long long e1 = ld_relaxed_u64(src + 1);
            unsigned long long e2 = ld_relaxed_u64(src + 2);
            unsigned long long e3 = ld_relaxed_u64(src + 3);
            while ((unsigned)(e0 >> 32) != tag || (unsigned)(e1 >> 32) != tag ||
                   (unsigned)(e2 >> 32) != tag || (unsigned)(e3 >> 32) != tag) {
                e0 = ld_relaxed_u64(src + 0);
                e1 = ld_relaxed_u64(src + 1);
                e2 = ld_relaxed_u64(src + 2);
                e3 = ld_relaxed_u64(src + 3);
            }
            hs4[tid] = make_float4(__uint_as_float((unsigned)e0),
                                   __uint_as_float((unsigned)e1),
                                   __uint_as_float((unsigned)e2),
                                   __uint_as_float((unsigned)e3));
            __syncthreads();

            // --- dual dot products with packed f32x2 FMAs
            const ulonglong2* hsu = reinterpret_cast<const ulonglong2*>(hs4);
            unsigned long long af01 = 0ull, af23 = 0ull, ah01 = 0ull, ah23 = 0ull;
            #pragma unroll
            for (int c = 0; c < 8; ++c) {
                const ulonglong2 hv = hsu[c * 32 + lane];   // LDS.128
                ffma2(af01, wfu[c].x, hv.x);
                ffma2(af23, wfu[c].y, hv.y);
                ffma2(ah01, whu[c].x, hv.x);
                ffma2(ah23, whu[c].y, hv.y);
            }
            const float2 fa = u2f(af01), fb = u2f(af23);
            const float2 ga = u2f(ah01), gb = u2f(ah23);
            float af = (fa.x + fa.y) + (fb.x + fb.y);
            float ah = (ga.x + ga.y) + (gb.x + gb.y);

            // prefetch next step's Xp — hides under reduce + poll
            float xf_n = 0.f, xh_n = 0.f;
            if (b + 1 < Bn) {
                xf_n = __ldg(xpf + (size_t)(b + 1) * Gn);
                xh_n = __ldg(xph + (size_t)(b + 1) * Gn);
            }

            #pragma unroll
            for (int off = 16; off > 0; off >>= 1) {
                af += __shfl_xor_sync(0xffffffffu, af, off);
                ah += __shfl_xor_sync(0xffffffffu, ah, off);
            }

            // fast gating (error ~1e-6, tolerance 1e-3); hprev from register
            const float fz = xf + af + bf;
            const float fG = __fdividef(1.0f, 1.0f + __expf(-fz));
            float ta = xh + fG * (ah + bh);
            ta = fminf(fmaxf(ta, -15.f), 15.f);
            const float e2v = __expf(2.0f * ta);
            const float hG = __fdividef(e2v - 1.0f, e2v + 1.0f);
            const float hnew = fmaf(fG, hG - hprev, hprev);
            hprev = hnew;     // identical on all lanes (af/ah fully reduced)

            if (lane == 0) {
                // publish (tag<<32 | value) as ONE 64-bit atom — never torn.
                // single-address red.release right after: forces drain AND
                // paces the grid (R10/R12/R13/R14 evidence: both matter).
                const unsigned long long atom =
                    ((unsigned long long)(unsigned)(b + 1) << 32) |
                    (unsigned long long)__float_as_uint(hnew);
                st_relaxed_u64(&g_hx[(b + 1) & 1][j], atom);
                g_lasts[(size_t)b * Hn + j] = hnew;
                bar_arrive_release(&g_bar[b]);     // for out-CTAs only
            }
            __syncthreads();   // all warps done reading hs4 before next stage

            xf = xf_n; xh = xh_n;
        }
    } else {
        // ----------------- output GEMV role -----------------
        const int o = (blockIdx.x - RGRID) * 8 + w;    // 0..127

        float4 wv[8];
        #pragma unroll
        for (int c = 0; c < 8; ++c)
            wv[c] = __ldg(reinterpret_cast<const float4*>(
                          Wout + (size_t)o * Hn) + c * 32 + lane);
        const float bo = __ldg(Bout + o);

        for (int b = 0; b < Bn; ++b) {
            if (tid == 0) {
                // ARRIVALS = RGRID*8: one release per recurrence warp
                while (ld_acquire_gpu(&g_bar[b]) < (unsigned)ARRIVALS) {}
            }
            __syncthreads();

            const float4* lr = reinterpret_cast<const float4*>(
                g_lasts + (size_t)b * Hn);
            float a0 = 0.f, a1 = 0.f, a2 = 0.f, a3 = 0.f;
            #pragma unroll
            for (int c = 0; c < 8; ++c) {
                const float4 lv = __ldcg(lr + c * 32 + lane);
                a0 = fmaf(wv[c].x, lv.x, a0);
                a1 = fmaf(wv[c].y, lv.y, a1);
                a2 = fmaf(wv[c].z, lv.z, a2);
                a3 = fmaf(wv[c].w, lv.w, a3);
            }
            float acc = (a0 + a1) + (a2 + a3);
            #pragma unroll
            for (int off = 16; off > 0; off >>= 1)
                acc += __shfl_xor_sync(0xffffffffu, acc, off);
            if (lane == 0) out[(size_t)b * On + o] = acc + bo;
        }
    }
}

// ---------------------------------------------------------------------------
extern "C" void kernel_launch(void* const* d_in, const int* in_sizes, int n_in,
                              void* d_out, int out_size) {
    const float* inputs = (const float*)d_in[0];
    const float* Wih    = (const float*)d_in[1];
    const float* Whh    = (const float*)d_in[2];
    const float* Bih    = (const float*)d_in[3];
    const float* Bhh    = (const float*)d_in[4];
    const float* Wout   = (const float*)d_in[5];
    const float* Bout   = (const float*)d_in[6];
    float* out = (float*)d_out;

    xproj_kernel<<<dim3(32, 8), 256>>>(inputs, Wih, Bih);
    recur_kernel<<<TGRID, 256>>>(Whh, Bhh, Wout, Bout, out);
}

// round 17
// speedup vs baseline: 1.6704x; 1.1182x over previous
#include <cuda_runtime.h>
#include <cstdint>

// Problem dims
#define Bn 256
#define Tn 512
#define In 256
#define Hn 1024
#define On 128
#define Gn 2048   // 2*H

#define RGRID 128            // recurrence CTAs
#define OGRID 16             // output-GEMV CTAs (consumers only)
#define TGRID (RGRID + OGRID)
#define ARRIVALS (RGRID * 8) // one release per recurrence WARP per step

// Scratch (static device globals — no allocation)
__device__ float              g_Xp[Bn * Gn];   // 2 MB : x-projection + Bih
__device__ unsigned long long g_hx[2][Hn];     // (tag<<32)|bits(h), dbl-buffered
__device__ float              g_lasts[Bn * Hn];// 1 MB : h after each step
__device__ unsigned           g_bar[Bn];       // per-step counters (out-CTAs)

// ---------------------------------------------------------------------------
// helpers
// ---------------------------------------------------------------------------
__device__ __forceinline__ void ffma2(unsigned long long& d,
                                      unsigned long long a,
                                      unsigned long long b) {
    asm("fma.rn.f32x2 %0, %1, %2, %0;" : "+l"(d) : "l"(a), "l"(b));
}
__device__ __forceinline__ float2 u2f(unsigned long long v) {
    float2 f; asm("mov.b64 {%0,%1}, %2;" : "=f"(f.x), "=f"(f.y) : "l"(v));
    return f;
}
__device__ __forceinline__ float4 ldcg_v4(const float4* p) {
    float4 v;
    asm volatile("ld.global.cg.v4.f32 {%0,%1,%2,%3}, [%4];"
                 : "=f"(v.x), "=f"(v.y), "=f"(v.z), "=f"(v.w)
                 : "l"(p) : "memory");
    return v;
}
// Hardware tanh (MUFU.TANH, sm_75+): one 16-cyc op replaces the
// __expf + __fdividef chain. Saturates correctly for all inputs.
__device__ __forceinline__ float tanh_approx(float a) {
    float d;
    asm("tanh.approx.f32 %0, %1;" : "=f"(d) : "f"(a));
    return d;
}
// single-access 64-bit atoms (value+tag travel together — never torn)
__device__ __forceinline__ unsigned long long ld_relaxed_u64(
        const unsigned long long* p) {
    unsigned long long v;
    asm volatile("ld.relaxed.gpu.global.b64 %0, [%1];"
                 : "=l"(v) : "l"(p) : "memory");
    return v;
}
__device__ __forceinline__ void st_relaxed_u64(unsigned long long* p,
                                               unsigned long long v) {
    asm volatile("st.relaxed.gpu.global.b64 [%0], %1;"
                 :: "l"(p), "l"(v) : "memory");
}
__device__ __forceinline__ void bar_arrive_release(unsigned* p) {
    asm volatile("red.release.gpu.global.add.u32 [%0], 1;" :: "l"(p) : "memory");
}
__device__ __forceinline__ unsigned ld_acquire_gpu(const unsigned* p) {
    unsigned v;
    asm volatile("ld.acquire.gpu.global.u32 %0, [%1];" : "=r"(v) : "l"(p) : "memory");
    return v;
}

// ---------------------------------------------------------------------------
// Phase 0: Xp[b, j] = dot(inputs[b, T-1, :], Wih[j, :]) + Bih[j]
// Register-tiled GEMM: grid (32 j-tiles of 64, 8 b-tiles of 32), 256 threads.
// Block (0,0) resets the tag buffers + counters so graph replays are
// deterministic.
// ---------------------------------------------------------------------------
__global__ void __launch_bounds__(256) xproj_kernel(
    const float* __restrict__ inputs, const float* __restrict__ Wih,
    const float* __restrict__ Bih)
{
    __shared__ float4 Xs4[32 * 65];          // 32 rows x 260 floats (pad 4)
    const int tid  = threadIdx.x;
    const int lane = tid & 31;
    const int jg   = tid >> 5;
    const int b0   = blockIdx.y * 32;

    if (blockIdx.x == 0 && blockIdx.y == 0) {
        g_bar[tid] = 0u;                     // 256 counters
        #pragma unroll
        for (int i = 0; i < 4; ++i) {        // 2 x 1024 u64, tag=0 value=0
            g_hx[0][tid + i * 256] = 0ull;
            g_hx[1][tid + i * 256] = 0ull;
        }
    }

    // Stage 32 input rows (last timestep of each b)
    #pragma unroll
    for (int i = 0; i < 8; ++i) {
        const int idx = tid + i * 256;       // 0..2047
        const int r   = idx >> 6;
        const int c4  = idx & 63;
        Xs4[r * 65 + c4] = ldcg_v4(reinterpret_cast<const float4*>(
            inputs + ((size_t)(b0 + r) * Tn + (Tn - 1)) * In) + c4);
    }
    __syncthreads();

    const int j0 = blockIdx.x * 64 + jg * 8;
    const float4* W4 = reinterpret_cast<const float4*>(Wih);

    unsigned long long acc[8][2];
    #pragma unroll
    for (int k = 0; k < 8; ++k) { acc[k][0] = 0ull; acc[k][1] = 0ull; }

    #pragma unroll 4
    for (int c4 = 0; c4 < 64; ++c4) {
        const float4 xv = Xs4[lane * 65 + c4];
        const ulonglong2 xu = *reinterpret_cast<const ulonglong2*>(&xv);
        #pragma unroll
        for (int k = 0; k < 8; ++k) {
            const float4 wv = __ldg(W4 + (size_t)(j0 + k) * 64 + c4);
            const ulonglong2 wu = *reinterpret_cast<const ulonglong2*>(&wv);
            ffma2(acc[k][0], wu.x, xu.x);
            ffma2(acc[k][1], wu.y, xu.y);
        }
    }

    float* dst = g_Xp + (size_t)(b0 + lane) * Gn + j0;
    #pragma unroll
    for (int k = 0; k < 8; ++k) {
        const float2 s0 = u2f(acc[k][0]);
        const float2 s1 = u2f(acc[k][1]);
        dst[k] = (s0.x + s0.y) + (s1.x + s1.y) + __ldg(Bih + j0 + k);
    }
}

// ---------------------------------------------------------------------------
// Phase 1+2 fused persistent kernel — the R15 configuration (proven local
// optimum: single-wave 4-atom poll, f32x2 dot, SHFL butterfly reduce, both
// __syncthreads, per-warp single-address red.release right after the tagged
// publish, register hprev) with ONE change: gating uses hardware
// tanh.approx.f32 (MUFU.TANH) for both the tanh and the sigmoid
// (sigmoid(x) = 0.5*tanh(x/2)+0.5) — removes two __expf chains and two
// divides (~130 cyc) from each serial step. Max err ~2e-5/step, contractive
// recurrence => terminal error well under the 1e-3 threshold.
//   CTAs [0,128): recurrence, warp owns j = cta*8 + w.
//   CTAs [128,144): output GEMV, warp owns o; spins on g_bar[b] reaching
//     ARRIVALS, then out[b,o] = dot(lasts[b,:], Wout[o,:]) + Bout[o].
// ---------------------------------------------------------------------------
__global__ void __launch_bounds__(256, 1) recur_kernel(
    const float* __restrict__ Whh, const float* __restrict__ Bhh,
    const float* __restrict__ Wout, const float* __restrict__ Bout,
    float* __restrict__ out)
{
    const int tid  = threadIdx.x;
    const int lane = tid & 31;
    const int w    = tid >> 5;

    if (blockIdx.x < RGRID) {
        // ----------------- recurrence role -----------------
        __shared__ float4 hs4[Hn / 4];            // 4 KB h staging (values only)
        const int j = blockIdx.x * 8 + w;         // 0..1023

        // Whh rows in registers as f32x2 pairs
        ulonglong2 wfu[8], whu[8];
        #pragma unroll
        for (int c = 0; c < 8; ++c) {
            float4 t0 = __ldg(reinterpret_cast<const float4*>(
                              Whh + (size_t)j * Hn) + c * 32 + lane);
            float4 t1 = __ldg(reinterpret_cast<const float4*>(
                              Whh + (size_t)(j + Hn) * Hn) + c * 32 + lane);
            wfu[c] = *reinterpret_cast<const ulonglong2*>(&t0);
            whu[c] = *reinterpret_cast<const ulonglong2*>(&t1);
        }
        const float bf = __ldg(Bhh + j);
        const float bh = __ldg(Bhh + j + Hn);

        // Xp pointers hoisted; first step's values prefetched
        const float* xpf = g_Xp + j;          // row stride Gn
        const float* xph = g_Xp + Hn + j;
        float xf = __ldg(xpf);
        float xh = __ldg(xph);

        float hprev = 0.0f;                   // own h[j], carried in register

        for (int b = 0; b < Bn; ++b) {
            // --- PARALLEL poll of tagged h atoms (thread owns 4 elements):
            // all four loads in flight together — ~1 L2 RT per pass.
            const unsigned tag = (unsigned)b;
            const unsigned long long* src = &g_hx[b & 1][4 * tid];
            unsigned long long e0 = ld_relaxed_u64(src + 0);
            unsigned long long e1 = ld_relaxed_u64(src + 1);
            unsigned long long e2 = ld_relaxed_u64(src + 2);
            unsigned long long e3 = ld_relaxed_u64(src + 3);
            while ((unsigned)(e0 >> 32) != tag || (unsigned)(e1 >> 32) != tag ||
                   (unsigned)(e2 >> 32) != tag || (unsigned)(e3 >> 32) != tag) {
                e0 = ld_relaxed_u64(src + 0);
                e1 = ld_relaxed_u64(src + 1);
                e2 = ld_relaxed_u64(src + 2);
                e3 = ld_relaxed_u64(src + 3);
            }
            hs4[tid] = make_float4(__uint_as_float((unsigned)e0),
                                   __uint_as_float((unsigned)e1),
                                   __uint_as_float((unsigned)e2),
                                   __uint_as_float((unsigned)e3));
            __syncthreads();

            // --- dual dot products with packed f32x2 FMAs
            const ulonglong2* hsu = reinterpret_cast<const ulonglong2*>(hs4);
            unsigned long long af01 = 0ull, af23 = 0ull, ah01 = 0ull, ah23 = 0ull;
            #pragma unroll
            for (int c = 0; c < 8; ++c) {
                const ulonglong2 hv = hsu[c * 32 + lane];   // LDS.128
                ffma2(af01, wfu[c].x, hv.x);
                ffma2(af23, wfu[c].y, hv.y);
                ffma2(ah01, whu[c].x, hv.x);
                ffma2(ah23, whu[c].y, hv.y);
            }
            const float2 fa = u2f(af01), fb = u2f(af23);
            const float2 ga = u2f(ah01), gb = u2f(ah23);
            float af = (fa.x + fa.y) + (fb.x + fb.y);
            float ah = (ga.x + ga.y) + (gb.x + gb.y);

            // prefetch next step's Xp — hides under reduce + poll
            float xf_n = 0.f, xh_n = 0.f;
            if (b + 1 < Bn) {
                xf_n = __ldg(xpf + (size_t)(b + 1) * Gn);
                xh_n = __ldg(xph + (size_t)(b + 1) * Gn);
            }

            #pragma unroll
            for (int off = 16; off > 0; off >>= 1) {
                af += __shfl_xor_sync(0xffffffffu, af, off);
                ah += __shfl_xor_sync(0xffffffffu, ah, off);
            }

            // hardware-tanh gating: sigmoid(x) = 0.5*tanh(0.5x)+0.5
            const float fz = xf + af + bf;
            const float fG = fmaf(0.5f, tanh_approx(0.5f * fz), 0.5f);
            const float ta = xh + fG * (ah + bh);
            const float hG = tanh_approx(ta);
            const float hnew = fmaf(fG, hG - hprev, hprev);
            hprev = hnew;     // identical on all lanes (af/ah fully reduced)

            if (lane == 0) {
                // publish (tag<<32 | value) as ONE 64-bit atom — never torn.
                // single-address red.release right after: forces drain AND
                // paces the grid (R10/R12/R13/R14 evidence: both matter).
                const unsigned long long atom =
                    ((unsigned long long)(unsigned)(b + 1) << 32) |
                    (unsigned long long)__float_as_uint(hnew);
                st_relaxed_u64(&g_hx[(b + 1) & 1][j], atom);
                g_lasts[(size_t)b * Hn + j] = hnew;
                bar_arrive_release(&g_bar[b]);     // for out-CTAs only
            }
            __syncthreads();   // all warps done reading hs4 before next stage

            xf = xf_n; xh = xh_n;
        }
    } else {
        // ----------------- output GEMV role -----------------
        const int o = (blockIdx.x - RGRID) * 8 + w;    // 0..127

        float4 wv[8];
        #pragma unroll
        for (int c = 0; c < 8; ++c)
            wv[c] = __ldg(reinterpret_cast<const float4*>(
                          Wout + (size_t)o * Hn) + c * 32 + lane);
        const float bo = __ldg(Bout + o);

        for (int b = 0; b < Bn; ++b) {
            if (tid == 0) {
                // ARRIVALS = RGRID*8: one release per recurrence warp
                while (ld_acquire_gpu(&g_bar[b]) < (unsigned)ARRIVALS) {}
            }
            __syncthreads();

            const float4* lr = reinterpret_cast<const float4*>(
                g_lasts + (size_t)b * Hn);
            float a0 = 0.f, a1 = 0.f, a2 = 0.f, a3 = 0.f;
            #pragma unroll
            for (int c = 0; c < 8; ++c) {
                const float4 lv = __ldcg(lr + c * 32 + lane);
                a0 = fmaf(wv[c].x, lv.x, a0);
                a1 = fmaf(wv[c].y, lv.y, a1);
                a2 = fmaf(wv[c].z, lv.z, a2);
                a3 = fmaf(wv[c].w, lv.w, a3);
            }
            float acc = (a0 + a1) + (a2 + a3);
            #pragma unroll
            for (int off = 16; off > 0; off >>= 1)
                acc += __shfl_xor_sync(0xffffffffu, acc, off);
            if (lane == 0) out[(size_t)b * On + o] = acc + bo;
        }
    }
}

// ---------------------------------------------------------------------------
extern "C" void kernel_launch(void* const* d_in, const int* in_sizes, int n_in,
                              void* d_out, int out_size) {
    const float* inputs = (const float*)d_in[0];
    const float* Wih    = (const float*)d_in[1];
    const float* Whh    = (const float*)d_in[2];
    const float* Bih    = (const float*)d_in[3];
    const float* Bhh    = (const float*)d_in[4];
    const float* Wout   = (const float*)d_in[5];
    const float* Bout   = (const float*)d_in[6];
    float* out = (float*)d_out;

    xproj_kernel<<<dim3(32, 8), 256>>>(inputs, Wih, Bih);
    recur_kernel<<<TGRID, 256>>>(Whh, Bhh, Wout, Bout, out);
}